// round 4
// baseline (speedup 1.0000x reference)
#include <cuda_runtime.h>
#include <cstdint>

// Inputs (metadata order):
//   d_in[0] state           float32 [B, A, N, 3]
//   d_in[1] nodes_coords    float32 [P, 2]
//   d_in[2] adj             float32 [P, N]
//   d_in[3] node_last_visit int32   [B, A]
//   d_in[4] patrol_index    int32   [P]
// Output: float32 [B, A, N, 6]
//
// out[r, n, 0:3] = state[r, n, :]
// out[r, n, 3:5] = nodes_coords[nlv[r], :]
// out[r, n, 5]   = adj[patrol_index[nlv[r]], n]

__global__ __launch_bounds__(128)
void policy_gather_kernel(const float* __restrict__ state,
                          const float* __restrict__ coords,
                          const float* __restrict__ adj,
                          const int*   __restrict__ nlv,
                          const int*   __restrict__ pidx,
                          float* __restrict__ out,
                          int N) {
    const int row = blockIdx.x;
    const int t   = threadIdx.x;

    // Row-constant gathers (L1/L2 resident, broadcast across the block).
    const int   v   = __ldg(nlv + row);
    const int   idx = __ldg(pidx + v);
    const float zx  = __ldg(coords + 2 * v);
    const float zy  = __ldg(coords + 2 * v + 1);

    const float* __restrict__ st = state + (size_t)row * N * 3;   // 3000B*row -> 8B aligned
    const float* __restrict__ ar = adj   + (size_t)idx * N;       // 1000B*idx -> 8B aligned
    float* __restrict__ orow     = out   + (size_t)row * N * 6;   // 6000B*row -> 16B aligned

    const bool okA = (((((uintptr_t)st) | ((uintptr_t)ar)) & 7) == 0) &&
                     ((((uintptr_t)orow) & 15) == 0);

    if (okA) {
        // One thread per node pair: 4 loads in registers -> 3 direct STG.128.
        const int pairs = N >> 1;
        for (int p = t; p < pairs; p += blockDim.x) {
            const float2 s01 = __ldcs(reinterpret_cast<const float2*>(st + 6 * p));
            const float2 s23 = __ldcs(reinterpret_cast<const float2*>(st + 6 * p + 2));
            const float2 s45 = __ldcs(reinterpret_cast<const float2*>(st + 6 * p + 4));
            const float2 aa  = __ldg (reinterpret_cast<const float2*>(ar + 2 * p));

            float4* __restrict__ d = reinterpret_cast<float4*>(orow + 12 * p);
            __stcs(d + 0, make_float4(s01.x, s01.y, s23.x, zx));   // n=2p:   s0 s1 s2 zx
            __stcs(d + 1, make_float4(zy,    aa.x,  s23.y, s45.x)); //        zy a0 | s3 s4
            __stcs(d + 2, make_float4(s45.y, zx,    zy,    aa.y)); // n=2p+1: s5 zx zy a1
        }
        // Odd-N tail node.
        if ((N & 1) && t == 0) {
            const int n = N - 1;
            float* d = orow + 6 * n;
            d[0] = st[3 * n + 0];
            d[1] = st[3 * n + 1];
            d[2] = st[3 * n + 2];
            d[3] = zx;
            d[4] = zy;
            d[5] = ar[n];
        }
    } else {
        // Scalar fallback (not taken for standard allocations).
        for (int n = t; n < N; n += blockDim.x) {
            float* d = orow + 6 * n;
            d[0] = st[3 * n + 0];
            d[1] = st[3 * n + 1];
            d[2] = st[3 * n + 2];
            d[3] = zx;
            d[4] = zy;
            d[5] = ar[n];
        }
    }
}

extern "C" void kernel_launch(void* const* d_in, const int* in_sizes, int n_in,
                              void* d_out, int out_size) {
    const float* state  = (const float*)d_in[0];
    const float* coords = (const float*)d_in[1];
    const float* adj    = (const float*)d_in[2];
    const int*   nlv    = (const int*)d_in[3];
    const int*   pidx   = (const int*)d_in[4];
    float*       out    = (float*)d_out;

    const int BA = in_sizes[3];            // B * A rows
    const int P  = in_sizes[4];            // patrol nodes
    const int N  = in_sizes[2] / P;        // graph size (adj is [P, N])

    policy_gather_kernel<<<BA, 128>>>(state, coords, adj, nlv, pidx, out, N);
}

// round 5
// speedup vs baseline: 1.1502x; 1.1502x over previous
#include <cuda_runtime.h>
#include <cstdint>

// Inputs (metadata order):
//   d_in[0] state           float32 [B, A, N, 3]
//   d_in[1] nodes_coords    float32 [P, 2]
//   d_in[2] adj             float32 [P, N]
//   d_in[3] node_last_visit int32   [B, A]
//   d_in[4] patrol_index    int32   [P]
// Output: float32 [B, A, N, 6]
//
// out[r, n, 0:3] = state[r, n, :]
// out[r, n, 3:5] = nodes_coords[nlv[r], :]
// out[r, n, 5]   = adj[patrol_index[nlv[r]], n]

__global__ __launch_bounds__(128)
void policy_gather_kernel(const float* __restrict__ state,
                          const float* __restrict__ coords,
                          const float* __restrict__ adj,
                          const int*   __restrict__ nlv,
                          const int*   __restrict__ pidx,
                          float* __restrict__ out,
                          int N) {
    extern __shared__ float s_row[];   // N * 6 floats, output-row layout (16B aligned)

    const int row = blockIdx.x;
    const int t   = threadIdx.x;

    // Row-constant gathers (L1/L2 resident, broadcast across the block).
    const int   v   = __ldg(nlv + row);
    const int   idx = __ldg(pidx + v);
    const float zx  = __ldg(coords + 2 * v);
    const float zy  = __ldg(coords + 2 * v + 1);

    const float* __restrict__ st = state + (size_t)row * N * 3;   // 3000B*row -> 8B aligned
    const float* __restrict__ ar = adj   + (size_t)idx * N;       // 1000B*idx -> 8B aligned
    float* __restrict__ orow     = out   + (size_t)row * N * 6;   // 6000B*row -> 16B aligned

    const bool okA = (((((uintptr_t)st) | ((uintptr_t)ar)) & 7) == 0);

    if (okA) {
        // Phase 1: one thread per node pair.
        // 3x LDG.64 (state) + 1x LDG.64 (adj) -> 3x STS.128 (output-layout tile).
        // STS.128 lane stride = 48B: within each 8-lane phase all banks distinct.
        const int pairs = N >> 1;
        for (int p = t; p < pairs; p += blockDim.x) {
            const float2 s01 = __ldcs(reinterpret_cast<const float2*>(st + 6 * p));
            const float2 s23 = __ldcs(reinterpret_cast<const float2*>(st + 6 * p + 2));
            const float2 s45 = __ldcs(reinterpret_cast<const float2*>(st + 6 * p + 4));
            const float2 aa  = __ldg (reinterpret_cast<const float2*>(ar + 2 * p));

            float4* d = reinterpret_cast<float4*>(s_row + 12 * p);  // 48B*p -> 16B aligned
            d[0] = make_float4(s01.x, s01.y, s23.x, zx);    // n=2p:   s0 s1 s2 zx
            d[1] = make_float4(zy,    aa.x,  s23.y, s45.x); //         zy a0 | s3 s4
            d[2] = make_float4(s45.y, zx,    zy,    aa.y);  // n=2p+1: s5 zx zy a1
        }
        // Odd-N tail node.
        if ((N & 1) && t == 0) {
            const int n = N - 1;
            float* d = s_row + 6 * n;
            d[0] = st[3 * n + 0];
            d[1] = st[3 * n + 1];
            d[2] = st[3 * n + 2];
            d[3] = zx;
            d[4] = zy;
            d[5] = ar[n];
        }
    } else {
        // Scalar fallback (not taken for standard allocations).
        for (int n = t; n < N; n += blockDim.x) {
            float* d = s_row + 6 * n;
            d[0] = st[3 * n + 0];
            d[1] = st[3 * n + 1];
            d[2] = st[3 * n + 2];
            d[3] = zx;
            d[4] = zy;
            d[5] = ar[n];
        }
    }
    __syncthreads();

    // Phase 2: fully coalesced float4 streaming store (evict-first).
    const int total = N * 6;
    if ((((uintptr_t)orow) & 0xF) == 0) {
        const int vec4 = total >> 2;
        float4* __restrict__ o4 = reinterpret_cast<float4*>(orow);
        const float4* __restrict__ s4 = reinterpret_cast<const float4*>(s_row);
        for (int j = t; j < vec4; j += blockDim.x) {
            __stcs(o4 + j, s4[j]);
        }
        for (int j = (vec4 << 2) + t; j < total; j += blockDim.x) {
            __stcs(orow + j, s_row[j]);
        }
    } else {
        for (int j = t; j < total; j += blockDim.x) {
            __stcs(orow + j, s_row[j]);
        }
    }
}

extern "C" void kernel_launch(void* const* d_in, const int* in_sizes, int n_in,
                              void* d_out, int out_size) {
    const float* state  = (const float*)d_in[0];
    const float* coords = (const float*)d_in[1];
    const float* adj    = (const float*)d_in[2];
    const int*   nlv    = (const int*)d_in[3];
    const int*   pidx   = (const int*)d_in[4];
    float*       out    = (float*)d_out;

    const int BA = in_sizes[3];            // B * A rows
    const int P  = in_sizes[4];            // patrol nodes
    const int N  = in_sizes[2] / P;        // graph size (adj is [P, N])

    const size_t smem = (size_t)N * 6 * sizeof(float);
    policy_gather_kernel<<<BA, 128, smem>>>(state, coords, adj, nlv, pidx, out, N);
}